// round 1
// baseline (speedup 1.0000x reference)
#include <cuda_runtime.h>
#include <cuda_bf16.h>

// Problem constants
#define S 8192
#define E 64
#define D 4096
#define CAP 128
#define SEC 67108864LL   // S*E*CAP

// ---------------- device scratch (no allocations allowed) ----------------
__device__ float g_logits[S * E];        // 2 MB
__device__ int   g_assign[S];
__device__ float g_topgate[S];
__device__ float g_cspart[256 * 64];     // per-block gate column sums
__device__ int   g_counts[64];

// ---------------- f32x2 helpers ----------------
__device__ __forceinline__ unsigned long long packdup(float a) {
    unsigned long long r;
    asm("mov.b64 %0, {%1, %2};" : "=l"(r) : "f"(a), "f"(a));
    return r;
}
__device__ __forceinline__ void fma2(unsigned long long& d, unsigned long long a, unsigned long long b) {
    asm("fma.rn.f32x2 %0, %1, %2, %0;" : "+l"(d) : "l"(a), "l"(b));
}
__device__ __forceinline__ void unpack2(unsigned long long v, float& lo, float& hi) {
    asm("mov.b64 {%0, %1}, %2;" : "=f"(lo), "=f"(hi) : "l"(v));
}

// ==========================================================================
// K1: zero the output buffer (overlaps with compute drain) + fp32 GEMM
//     logits[t][e] = dot(x[t,:], w[e,:]),  tile 64 tokens x 64 experts, BK=32
//     grid 128 blocks x 128 threads, f32x2 packed FMA, double-buffered smem.
// ==========================================================================
__global__ __launch_bounds__(128) void k1_gemm(const float* __restrict__ x,
                                               const float* __restrict__ w,
                                               float* __restrict__ out,
                                               long long out_n) {
    const int tid = threadIdx.x;
    const int gtid = blockIdx.x * 128 + tid;

    // ---- phase A: zero output (stores drain in background during GEMM) ----
    {
        const long long nv4 = out_n >> 2;
        const float4 z = make_float4(0.f, 0.f, 0.f, 0.f);
        for (long long i = gtid; i < nv4; i += 128LL * 128LL)
            reinterpret_cast<float4*>(out)[i] = z;
        if (gtid == 0) {
            for (long long i = (nv4 << 2); i < out_n; i++) out[i] = 0.f;
            for (int e = 0; e < 64; e++) g_counts[e] = 0;
        }
    }

    // ---- phase B: GEMM ----
    __shared__ __align__(16) float xs[2][32][66];  // [buf][k][token] (stride 66: 2-way max)
    __shared__ __align__(16) float ws[2][32][65];  // [buf][k][expert] (stride 65: conflict-free)

    const int t0 = blockIdx.x * 64;
    const int tm = tid & 7;    // token group: tokens 8*tm .. 8*tm+7
    const int tn = tid >> 3;   // expert group: experts 4*tn .. 4*tn+3

    // preload k-step 0
    {
        const int k0 = 0;
#pragma unroll
        for (int r = 0; r < 4; r++) {
            int idx = tid + r * 128;           // 0..511
            int row = idx >> 3;                // 0..63
            int kq  = (idx & 7) << 2;          // 0,4,...,28
            float4 xv = *reinterpret_cast<const float4*>(&x[(size_t)(t0 + row) * D + k0 + kq]);
            xs[0][kq + 0][row] = xv.x; xs[0][kq + 1][row] = xv.y;
            xs[0][kq + 2][row] = xv.z; xs[0][kq + 3][row] = xv.w;
            float4 wv = *reinterpret_cast<const float4*>(&w[(size_t)row * D + k0 + kq]);
            ws[0][kq + 0][row] = wv.x; ws[0][kq + 1][row] = wv.y;
            ws[0][kq + 2][row] = wv.z; ws[0][kq + 3][row] = wv.w;
        }
    }
    __syncthreads();

    unsigned long long acc[4][4];
#pragma unroll
    for (int i = 0; i < 4; i++)
#pragma unroll
        for (int j = 0; j < 4; j++) acc[i][j] = 0ULL;

    const int NKB = D / 32;  // 128
    for (int kb = 0; kb < NKB; kb++) {
        const int buf = kb & 1;
        float4 px[4], pw[4];
        if (kb + 1 < NKB) {
            const int k0 = (kb + 1) * 32;
#pragma unroll
            for (int r = 0; r < 4; r++) {
                int idx = tid + r * 128;
                int row = idx >> 3;
                int kq  = (idx & 7) << 2;
                px[r] = *reinterpret_cast<const float4*>(&x[(size_t)(t0 + row) * D + k0 + kq]);
                pw[r] = *reinterpret_cast<const float4*>(&w[(size_t)row * D + k0 + kq]);
            }
        }
#pragma unroll
        for (int kk = 0; kk < 32; kk++) {
            unsigned long long xp[4];
#pragma unroll
            for (int i = 0; i < 4; i++)
                xp[i] = *reinterpret_cast<const unsigned long long*>(&xs[buf][kk][8 * tm + 2 * i]);
#pragma unroll
            for (int j = 0; j < 4; j++) {
                unsigned long long wp = packdup(ws[buf][kk][4 * tn + j]);
#pragma unroll
                for (int i = 0; i < 4; i++) fma2(acc[i][j], xp[i], wp);
            }
        }
        if (kb + 1 < NKB) {
            const int nb = buf ^ 1;
#pragma unroll
            for (int r = 0; r < 4; r++) {
                int idx = tid + r * 128;
                int row = idx >> 3;
                int kq  = (idx & 7) << 2;
                xs[nb][kq + 0][row] = px[r].x; xs[nb][kq + 1][row] = px[r].y;
                xs[nb][kq + 2][row] = px[r].z; xs[nb][kq + 3][row] = px[r].w;
                ws[nb][kq + 0][row] = pw[r].x; ws[nb][kq + 1][row] = pw[r].y;
                ws[nb][kq + 2][row] = pw[r].z; ws[nb][kq + 3][row] = pw[r].w;
            }
        }
        __syncthreads();
    }

    // write logits
#pragma unroll
    for (int i = 0; i < 4; i++) {
#pragma unroll
        for (int j = 0; j < 4; j++) {
            float lo, hi;
            unpack2(acc[i][j], lo, hi);
            int t = t0 + 8 * tm + 2 * i;
            int e = 4 * tn + j;
            g_logits[(size_t)t * E + e]       = lo;
            g_logits[(size_t)(t + 1) * E + e] = hi;
        }
    }
}

// ==========================================================================
// K2: per-token softmax + argmax (first-occurrence tie-break), per-block
//     column-sum partials + per-expert counts. 256 blocks x 1024 threads
//     (one warp per token, 2 logits per lane).
// ==========================================================================
__global__ __launch_bounds__(1024) void k2_gate() {
    __shared__ float cs[64];
    __shared__ int   cnt[64];
    const int tid = threadIdx.x;
    if (tid < 64) { cs[tid] = 0.f; cnt[tid] = 0; }
    __syncthreads();

    const int wid = tid >> 5, lane = tid & 31;
    const int t = blockIdx.x * 32 + wid;

    float l0 = g_logits[(size_t)t * E + lane];
    float l1 = g_logits[(size_t)t * E + 32 + lane];

    float bv; int bi;
    if (l0 >= l1) { bv = l0; bi = lane; } else { bv = l1; bi = lane + 32; }
#pragma unroll
    for (int o = 16; o; o >>= 1) {
        float ov = __shfl_xor_sync(0xFFFFFFFFu, bv, o);
        int   oi = __shfl_xor_sync(0xFFFFFFFFu, bi, o);
        if (ov > bv || (ov == bv && oi < bi)) { bv = ov; bi = oi; }
    }
    float e0 = __expf(l0 - bv), e1 = __expf(l1 - bv);
    float z = e0 + e1;
#pragma unroll
    for (int o = 16; o; o >>= 1) z += __shfl_xor_sync(0xFFFFFFFFu, z, o);
    float inv = 1.0f / z;

    atomicAdd(&cs[lane],      e0 * inv);
    atomicAdd(&cs[lane + 32], e1 * inv);
    if (lane == 0) {
        g_assign[t]  = bi;
        g_topgate[t] = inv;       // gate value at argmax = exp(0)/Z
        atomicAdd(&cnt[bi], 1);
    }
    __syncthreads();
    if (tid < 64) {
        g_cspart[blockIdx.x * 64 + tid] = cs[tid];
        atomicAdd(&g_counts[tid], cnt[tid]);
    }
}

// ==========================================================================
// K3: per-expert exact top_k(capacity) replication + cumsum slots + scatter.
//     Column values v[t] = assigned ? bits(noise) : 0 over ALL tokens;
//     threshold T = 128th largest v (binary search on float bits), ties
//     broken by lower token index (matches jax.lax.top_k). 64 blocks x 256.
// ==========================================================================
__global__ __launch_bounds__(256) void k3_select(const float* __restrict__ noise,
                                                 float* __restrict__ out,
                                                 long long out_n) {
    const int e = blockIdx.x;
    const int tid = threadIdx.x;
    const int lane = tid & 31, wid = tid >> 5;
    __shared__ int red[8];
    __shared__ int weq[8], wkp[8];

    // binary search: largest T with count(v >= T) >= CAP  (T=0 trivially ok: 8192)
    unsigned lo = 0u, hi = 0x3F7FFFFFu;
    while (lo < hi) {
        unsigned mid = lo + ((hi - lo + 1) >> 1);   // mid >= 1
        int c = 0;
        for (int t = tid; t < S; t += 256) {
            if (g_assign[t] == e) {
                unsigned b = __float_as_uint(noise[(size_t)t * E + e]);
                c += (b >= mid);
            }
        }
#pragma unroll
        for (int o = 16; o; o >>= 1) c += __shfl_xor_sync(0xFFFFFFFFu, c, o);
        if (lane == 0) red[wid] = c;
        __syncthreads();
        int tot = 0;
#pragma unroll
        for (int i = 0; i < 8; i++) tot += red[i];
        __syncthreads();
        if (tot >= CAP) lo = mid; else hi = mid - 1;
    }
    const unsigned T = lo;

    // k_gt = count(v > T) = count(v >= T+1)
    int kg;
    {
        const unsigned q = T + 1u;
        int c = 0;
        for (int t = tid; t < S; t += 256) {
            if (g_assign[t] == e) {
                unsigned b = __float_as_uint(noise[(size_t)t * E + e]);
                c += (b >= q);
            }
        }
#pragma unroll
        for (int o = 16; o; o >>= 1) c += __shfl_xor_sync(0xFFFFFFFFu, c, o);
        if (lane == 0) red[wid] = c;
        __syncthreads();
        int tot = 0;
#pragma unroll
        for (int i = 0; i < 8; i++) tot += red[i];
        kg = tot;
        __syncthreads();
    }
    const int remaining = CAP - kg;  // >= 1 slots for v == T, taken by lowest index

    // ordered pass: equal-rank tie-break + cumsum slot assignment + scatter
    int base = 0, eqbase = 0;
    for (int c0 = 0; c0 < S; c0 += 256) {
        const int t = c0 + tid;
        const int a = (g_assign[t] == e);
        unsigned v = 0u;
        if (a) v = __float_as_uint(noise[(size_t)t * E + e]);
        const bool gt = (v > T);
        const bool eq = (v == T);

        unsigned beq = __ballot_sync(0xFFFFFFFFu, eq);
        if (lane == 0) weq[wid] = __popc(beq);
        __syncthreads();
        int eqoff = 0;
        for (int i = 0; i < wid; i++) eqoff += weq[i];
        int eqtot = 0;
#pragma unroll
        for (int i = 0; i < 8; i++) eqtot += weq[i];
        const int eqrank = eqbase + eqoff + __popc(beq & ((1u << lane) - 1u));

        const bool kept = a && (gt || (eq && eqrank < remaining));
        unsigned bk = __ballot_sync(0xFFFFFFFFu, kept);
        if (lane == 0) wkp[wid] = __popc(bk);
        __syncthreads();
        int koff = 0;
        for (int i = 0; i < wid; i++) koff += wkp[i];
        int ktot = 0;
#pragma unroll
        for (int i = 0; i < 8; i++) ktot += wkp[i];

        if (kept) {
            const int slot = base + koff + __popc(bk & ((1u << lane) - 1u));
            const long long off = ((long long)t * E + e) * (long long)CAP + slot;
            if (1 + off < out_n)       out[1 + off]       = g_topgate[t];  // combine_weights
            if (1 + SEC + off < out_n) out[1 + SEC + off] = 1.0f;          // dispatch_mask
        }
        base   += ktot;
        eqbase += eqtot;
        __syncthreads();
    }
}

// ==========================================================================
// K4: l_aux + exp_counts (deterministic fixed-order reductions).
// ==========================================================================
__global__ __launch_bounds__(256) void k4_finalize(float* __restrict__ out, long long out_n) {
    __shared__ float ps[256];
    __shared__ float contrib[64];
    const int tid = threadIdx.x;
    const int e = tid >> 2, q = tid & 3;
    float s = 0.f;
    for (int b = q * 64; b < q * 64 + 64; b++) s += g_cspart[b * 64 + e];
    ps[tid] = s;
    __syncthreads();
    if (tid < 64) {
        float me = (ps[tid * 4] + ps[tid * 4 + 1] + ps[tid * 4 + 2] + ps[tid * 4 + 3]) / (float)S;
        float ce = (float)g_counts[tid] / (float)S;
        contrib[tid] = me * ce * (float)E;
        long long idx = 1 + 2 * SEC + tid;
        if (idx < out_n) out[idx] = (float)g_counts[tid];
    }
    __syncthreads();
    if (tid == 0) {
        float l = 0.f;
        for (int i = 0; i < 64; i++) l += contrib[i];
        out[0] = l;
    }
}

// ==========================================================================
extern "C" void kernel_launch(void* const* d_in, const int* in_sizes, int n_in,
                              void* d_out, int out_size) {
    const float* x     = (const float*)d_in[0];
    const float* w     = (const float*)d_in[1];
    const float* noise = (const float*)d_in[2];
    float* out = (float*)d_out;
    const long long n = (long long)out_size;

    k1_gemm<<<128, 128>>>(x, w, out, n);
    k2_gate<<<256, 1024>>>();
    k3_select<<<64, 256>>>(noise, out, n);
    k4_finalize<<<1, 256>>>(out, n);
}

// round 4
// speedup vs baseline: 1.2902x; 1.2902x over previous
#include <cuda_runtime.h>
#include <cuda_bf16.h>

// Problem constants
#define S 8192
#define E 64
#define D 4096
#define CAP 128
#define SE 524288          // S*E
#define SEC 67108864LL     // S*E*CAP

#define GEMM_BLOCKS 512
#define ZERO_BLOCKS 1536
#define TOTAL_BLOCKS (GEMM_BLOCKS + ZERO_BLOCKS)

#define K3_SMEM_CAP 4096   // smem compaction capacity per expert

// ---------------- device scratch (no allocations allowed) ----------------
__device__ float g_part[4 * SE];        // split-K partial logits (8 MB)
__device__ int   g_assign[S];
__device__ float g_topgate[S];
__device__ int   g_slotpack[S];         // (e<<7)|slot if kept, else -1
__device__ float g_cspart[1024 * 64];   // per-block gate column sums
__device__ int   g_counts[64];
__device__ float g_laux;

// ---------------- f32x2 helpers ----------------
__device__ __forceinline__ unsigned long long packdup(float a) {
    unsigned long long r;
    asm("mov.b64 %0, {%1, %2};" : "=l"(r) : "f"(a), "f"(a));
    return r;
}
__device__ __forceinline__ void fma2(unsigned long long& d, unsigned long long a, unsigned long long b) {
    asm("fma.rn.f32x2 %0, %1, %2, %0;" : "+l"(d) : "l"(a), "l"(b));
}
__device__ __forceinline__ void unpack2(unsigned long long v, float& lo, float& hi) {
    asm("mov.b64 {%0, %1}, %2;" : "=f"(lo), "=f"(hi) : "l"(v));
}

// ==========================================================================
// K1 (fused): blocks [0,512): fp32 split-K GEMM (128 token-blocks x 4 K-parts,
//             tile 64x64xK=1024, 128 threads, f32x2 packed FMA).
//             blocks [512,2048): grid-stride float4 zero-fill of the 536 MB
//             output — drains on the store path WHILE the GEMM crunches.
// ==========================================================================
__global__ __launch_bounds__(128, 4) void k1_fused(const float* __restrict__ x,
                                                   const float* __restrict__ w,
                                                   float* __restrict__ out,
                                                   long long out_n) {
    const int tid = threadIdx.x;

    if (blockIdx.x >= GEMM_BLOCKS) {
        // ---------------- zero-fill part ----------------
        const int zb = blockIdx.x - GEMM_BLOCKS;
        if (zb == 0 && tid == 0) {
            for (int e = 0; e < 64; e++) g_counts[e] = 0;
        }
        const long long nv4 = out_n >> 2;   // tail elem lands in exp_counts, rewritten by k5
        const long long stride = (long long)ZERO_BLOCKS * 128;
        const float4 z = make_float4(0.f, 0.f, 0.f, 0.f);
        for (long long i = (long long)zb * 128 + tid; i < nv4; i += stride)
            reinterpret_cast<float4*>(out)[i] = z;
        return;
    }

    // ---------------- GEMM part ----------------
    const int kp = blockIdx.x & 3;
    const int tb = blockIdx.x >> 2;
    const int t0 = tb * 64;
    const int kbase = kp * 1024;

    __shared__ __align__(16) float xs[2][32][66];
    __shared__ __align__(16) float ws[2][32][65];

    const int tm = tid & 7;    // token group
    const int tn = tid >> 3;   // expert group

    // preload k-step 0
    {
#pragma unroll
        for (int r = 0; r < 4; r++) {
            int idx = tid + r * 128;
            int row = idx >> 3;
            int kq  = (idx & 7) << 2;
            float4 xv = *reinterpret_cast<const float4*>(&x[(size_t)(t0 + row) * D + kbase + kq]);
            xs[0][kq + 0][row] = xv.x; xs[0][kq + 1][row] = xv.y;
            xs[0][kq + 2][row] = xv.z; xs[0][kq + 3][row] = xv.w;
            float4 wv = *reinterpret_cast<const float4*>(&w[(size_t)row * D + kbase + kq]);
            ws[0][kq + 0][row] = wv.x; ws[0][kq + 1][row] = wv.y;
            ws[0][kq + 2][row] = wv.z; ws[0][kq + 3][row] = wv.w;
        }
    }
    __syncthreads();

    unsigned long long acc[4][4];
#pragma unroll
    for (int i = 0; i < 4; i++)
#pragma unroll
        for (int j = 0; j < 4; j++) acc[i][j] = 0ULL;

    const int NKB = 1024 / 32;  // 32
    for (int kb = 0; kb < NKB; kb++) {
        const int buf = kb & 1;
        float4 px[4], pw[4];
        if (kb + 1 < NKB) {
            const int k0 = kbase + (kb + 1) * 32;
#pragma unroll
            for (int r = 0; r < 4; r++) {
                int idx = tid + r * 128;
                int row = idx >> 3;
                int kq  = (idx & 7) << 2;
                px[r] = *reinterpret_cast<const float4*>(&x[(size_t)(t0 + row) * D + k0 + kq]);
                pw[r] = *reinterpret_cast<const float4*>(&w[(size_t)row * D + k0 + kq]);
            }
        }
#pragma unroll
        for (int kk = 0; kk < 32; kk++) {
            unsigned long long xp[4];
#pragma unroll
            for (int i = 0; i < 4; i++)
                xp[i] = *reinterpret_cast<const unsigned long long*>(&xs[buf][kk][8 * tm + 2 * i]);
#pragma unroll
            for (int j = 0; j < 4; j++) {
                unsigned long long wp = packdup(ws[buf][kk][4 * tn + j]);
#pragma unroll
                for (int i = 0; i < 4; i++) fma2(acc[i][j], xp[i], wp);
            }
        }
        if (kb + 1 < NKB) {
            const int nb = buf ^ 1;
#pragma unroll
            for (int r = 0; r < 4; r++) {
                int idx = tid + r * 128;
                int row = idx >> 3;
                int kq  = (idx & 7) << 2;
                xs[nb][kq + 0][row] = px[r].x; xs[nb][kq + 1][row] = px[r].y;
                xs[nb][kq + 2][row] = px[r].z; xs[nb][kq + 3][row] = px[r].w;
                ws[nb][kq + 0][row] = pw[r].x; ws[nb][kq + 1][row] = pw[r].y;
                ws[nb][kq + 2][row] = pw[r].z; ws[nb][kq + 3][row] = pw[r].w;
            }
        }
        __syncthreads();
    }

    // write partials
    float* part = &g_part[(size_t)kp * SE];
#pragma unroll
    for (int i = 0; i < 4; i++) {
#pragma unroll
        for (int j = 0; j < 4; j++) {
            float lo, hi;
            unpack2(acc[i][j], lo, hi);
            int t = t0 + 8 * tm + 2 * i;
            int e = 4 * tn + j;
            part[(size_t)t * E + e]       = lo;
            part[(size_t)(t + 1) * E + e] = hi;
        }
    }
}

// ==========================================================================
// K2: sum split-K partials, softmax + argmax per token, per-block column
//     sums + per-expert counts. grid 1024 x 256 (one warp per token).
// ==========================================================================
__global__ __launch_bounds__(256) void k2_gate() {
    __shared__ float cs[64];
    __shared__ int   cnt[64];
    const int tid = threadIdx.x;
    if (tid < 64) { cs[tid] = 0.f; cnt[tid] = 0; }
    __syncthreads();

    const int wid = tid >> 5, lane = tid & 31;
    const int t = blockIdx.x * 8 + wid;
    const size_t b = (size_t)t * E;

    float l0 = 0.f, l1 = 0.f;
#pragma unroll
    for (int p = 0; p < 4; p++) {
        l0 += g_part[(size_t)p * SE + b + lane];
        l1 += g_part[(size_t)p * SE + b + 32 + lane];
    }

    float bv; int bi;
    if (l0 >= l1) { bv = l0; bi = lane; } else { bv = l1; bi = lane + 32; }
#pragma unroll
    for (int o = 16; o; o >>= 1) {
        float ov = __shfl_xor_sync(0xFFFFFFFFu, bv, o);
        int   oi = __shfl_xor_sync(0xFFFFFFFFu, bi, o);
        if (ov > bv || (ov == bv && oi < bi)) { bv = ov; bi = oi; }
    }
    float e0 = __expf(l0 - bv), e1 = __expf(l1 - bv);
    float z = e0 + e1;
#pragma unroll
    for (int o = 16; o; o >>= 1) z += __shfl_xor_sync(0xFFFFFFFFu, z, o);
    float inv = 1.0f / z;

    atomicAdd(&cs[lane],      e0 * inv);
    atomicAdd(&cs[lane + 32], e1 * inv);
    if (lane == 0) {
        g_assign[t]   = bi;
        g_topgate[t]  = inv;
        g_slotpack[t] = -1;
        atomicAdd(&cnt[bi], 1);
    }
    __syncthreads();
    if (tid < 64) {
        g_cspart[blockIdx.x * 64 + tid] = cs[tid];
        atomicAdd(&g_counts[tid], cnt[tid]);
    }
}

// ==========================================================================
// K3: blocks 0..63: per-expert top-CAP selection. Static smem compaction
//     (capacity 4096; expected ne ~ 128) + bit-threshold binary search +
//     exact tie-break + cumsum slots. Global-memory fallback if ne > 4096.
//     Writes g_slotpack[t] only. block 64: l_aux finalize.
//     All shared memory STATIC (~26 KB) — no dynamic smem, launch-safe.
// ==========================================================================
__global__ __launch_bounds__(256) void k3_select(const float* __restrict__ noise) {
    const int tid = threadIdx.x;
    const int lane = tid & 31, wid = tid >> 5;

    __shared__ unsigned bits[K3_SMEM_CAP];        // 16 KB
    __shared__ unsigned short tok[K3_SMEM_CAP];   // 8 KB
    __shared__ int red[8];
    __shared__ int weq[8], wkp[8];
    __shared__ int sh_ne;
    __shared__ float ps[256];
    __shared__ float contrib[64];

    if (blockIdx.x == 64) {
        // ---- l_aux finalize ----
        const int eidx = tid >> 2, q = tid & 3;
        float s = 0.f;
        for (int bkt = q * 256; bkt < q * 256 + 256; bkt++) s += g_cspart[bkt * 64 + eidx];
        ps[tid] = s;
        __syncthreads();
        if (tid < 64) {
            float me = (ps[tid * 4] + ps[tid * 4 + 1] + ps[tid * 4 + 2] + ps[tid * 4 + 3]) / (float)S;
            float ce = (float)g_counts[tid] / (float)S;
            contrib[tid] = me * ce * (float)E;
        }
        __syncthreads();
        if (tid == 0) {
            float l = 0.f;
            for (int i = 0; i < 64; i++) l += contrib[i];
            g_laux = l;
        }
        return;
    }

    const int e = blockIdx.x;

    // ---- pass 1: ordered compaction of (bits, token) for assigned tokens ----
    int base = 0;
    for (int c0 = 0; c0 < S; c0 += 256) {
        const int t = c0 + tid;
        const bool a = (g_assign[t] == e);
        unsigned b = 0u;
        if (a) b = __float_as_uint(noise[(size_t)t * E + e]);
        unsigned bal = __ballot_sync(0xFFFFFFFFu, a);
        if (lane == 0) red[wid] = __popc(bal);
        __syncthreads();
        int off = 0;
        for (int i = 0; i < wid; i++) off += red[i];
        int tot = 0;
#pragma unroll
        for (int i = 0; i < 8; i++) tot += red[i];
        if (a) {
            int pos = base + off + __popc(bal & ((1u << lane) - 1u));
            if (pos < K3_SMEM_CAP) {    // overflow-safe; fallback handles pos>=cap
                bits[pos] = b;
                tok[pos]  = (unsigned short)t;
            }
        }
        base += tot;
        __syncthreads();
    }
    if (tid == 0) sh_ne = base;
    __syncthreads();
    const int ne = sh_ne;
    const bool smem_ok = (ne <= K3_SMEM_CAP);

    // ---- pass 2: binary search for threshold T ----
    unsigned lo = 0u, hi = 0x3F7FFFFFu;
    while (lo < hi) {
        unsigned mid = lo + ((hi - lo + 1) >> 1);   // mid >= 1
        int c = 0;
        if (smem_ok) {
            for (int i = tid; i < ne; i += 256) c += (bits[i] >= mid);
        } else {
            for (int t = tid; t < S; t += 256)
                if (g_assign[t] == e)
                    c += (__float_as_uint(noise[(size_t)t * E + e]) >= mid);
        }
#pragma unroll
        for (int o = 16; o; o >>= 1) c += __shfl_xor_sync(0xFFFFFFFFu, c, o);
        if (lane == 0) red[wid] = c;
        __syncthreads();
        int tot = 0;
#pragma unroll
        for (int i = 0; i < 8; i++) tot += red[i];
        __syncthreads();
        if (tot >= CAP) lo = mid; else hi = mid - 1;
    }
    const unsigned T = lo;

    // ---- pass 3: count strictly-greater ----
    int kg;
    {
        int c = 0;
        const unsigned q = T + 1u;
        if (smem_ok) {
            for (int i = tid; i < ne; i += 256) c += (bits[i] >= q);
        } else {
            for (int t = tid; t < S; t += 256)
                if (g_assign[t] == e)
                    c += (__float_as_uint(noise[(size_t)t * E + e]) >= q);
        }
#pragma unroll
        for (int o = 16; o; o >>= 1) c += __shfl_xor_sync(0xFFFFFFFFu, c, o);
        if (lane == 0) red[wid] = c;
        __syncthreads();
        int tot = 0;
#pragma unroll
        for (int i = 0; i < 8; i++) tot += red[i];
        kg = tot;
        __syncthreads();
    }
    const int remaining = CAP - kg;

    if (smem_ok && T > 0u) {
        // ---- pass 4 (fast): ordered walk of compacted list in shared ----
        int kbase = 0, eqbase = 0;
        const int chunks = (ne + 255) >> 8;
        for (int ch = 0; ch < chunks; ch++) {
            const int i = ch * 256 + tid;
            const bool valid = (i < ne);
            unsigned v = valid ? bits[i] : 0u;
            const bool gt = valid && (v > T);
            const bool eq = valid && (v == T);

            unsigned beq = __ballot_sync(0xFFFFFFFFu, eq);
            if (lane == 0) weq[wid] = __popc(beq);
            __syncthreads();
            int eqoff = 0;
            for (int k = 0; k < wid; k++) eqoff += weq[k];
            int eqtot = 0;
#pragma unroll
            for (int k = 0; k < 8; k++) eqtot += weq[k];
            const int eqrank = eqbase + eqoff + __popc(beq & ((1u << lane) - 1u));

            const bool kept = gt || (eq && eqrank < remaining);
            unsigned bk = __ballot_sync(0xFFFFFFFFu, kept);
            if (lane == 0) wkp[wid] = __popc(bk);
            __syncthreads();
            int koff = 0;
            for (int k = 0; k < wid; k++) koff += wkp[k];
            int ktot = 0;
#pragma unroll
            for (int k = 0; k < 8; k++) ktot += wkp[k];

            if (kept) {
                const int slot = kbase + koff + __popc(bk & ((1u << lane) - 1u));
                g_slotpack[tok[i]] = (e << 7) | slot;
            }
            kbase  += ktot;
            eqbase += eqtot;
            __syncthreads();
        }
    } else {
        // ---- pass 4 (general): full global scan. Covers T==0 (zero-valued
        //      ties include unassigned tokens, matching top_k semantics) and
        //      the ne>cap fallback. ----
        int kbase = 0, eqbase = 0;
        for (int c0 = 0; c0 < S; c0 += 256) {
            const int t = c0 + tid;
            const bool a = (g_assign[t] == e);
            unsigned v = 0u;
            if (a) v = __float_as_uint(noise[(size_t)t * E + e]);
            const bool gt = a && (v > T);
            const bool eq = (v == T);   // for T==0 this includes unassigned tokens

            unsigned beq = __ballot_sync(0xFFFFFFFFu, eq);
            if (lane == 0) weq[wid] = __popc(beq);
            __syncthreads();
            int eqoff = 0;
            for (int k = 0; k < wid; k++) eqoff += weq[k];
            int eqtot = 0;
#pragma unroll
            for (int k = 0; k < 8; k++) eqtot += weq[k];
            const int eqrank = eqbase + eqoff + __popc(beq & ((1u << lane) - 1u));

            const bool kept = a && (gt || (eq && eqrank < remaining));
            unsigned bk = __ballot_sync(0xFFFFFFFFu, kept);
            if (lane == 0) wkp[wid] = __popc(bk);
            __syncthreads();
            int koff = 0;
            for (int k = 0; k < wid; k++) koff += wkp[k];
            int ktot = 0;
#pragma unroll
            for (int k = 0; k < 8; k++) ktot += wkp[k];

            if (kept) {
                const int slot = kbase + koff + __popc(bk & ((1u << lane) - 1u));
                g_slotpack[t] = (e << 7) | slot;
            }
            kbase  += ktot;
            eqbase += eqtot;
            __syncthreads();
        }
    }
}

// ==========================================================================
// K5: scatter of nonzeros + counts + l_aux into zeroed output.
// ==========================================================================
__global__ __launch_bounds__(256) void k5_scatter(float* __restrict__ out, long long out_n) {
    const int g = blockIdx.x * 256 + threadIdx.x;
    if (g < S) {
        const int p = g_slotpack[g];
        if (p >= 0) {
            const long long off = ((long long)g * E + (p >> 7)) * (long long)CAP + (p & 127);
            out[1 + off]       = g_topgate[g];   // combine_weights
            out[1 + SEC + off] = 1.0f;           // dispatch_mask
        }
    } else if (g < S + 64) {
        out[1 + 2 * SEC + (g - S)] = (float)g_counts[g - S];
    } else if (g == S + 64) {
        out[0] = g_laux;
    }
}

// ==========================================================================
extern "C" void kernel_launch(void* const* d_in, const int* in_sizes, int n_in,
                              void* d_out, int out_size) {
    const float* x     = (const float*)d_in[0];
    const float* w     = (const float*)d_in[1];
    const float* noise = (const float*)d_in[2];
    float* out = (float*)d_out;
    const long long n = (long long)out_size;

    k1_fused<<<TOTAL_BLOCKS, 128>>>(x, w, out, n);
    k2_gate<<<1024, 256>>>();
    k3_select<<<65, 256>>>(noise);
    k5_scatter<<<33, 256>>>(out, n);
}